// round 4
// baseline (speedup 1.0000x reference)
#include <cuda_runtime.h>
#include <math.h>

// Fused: binarized-conv(3x3,Cin=1,Cout=32,SAME) + global-avg-pool + dense(32->10) + softmax.
// pooling commutes with conv: p[b,co] = conv_b[co] + (1/4096)*sum_k sign(w[k,co])*S[b,k],
// S[b,k] = 9 shifted sums derived from {total, row0, row63, col0, col63, 4 corners}.
//
// One warp per image, one block per warp, grid=512 => all CTAs resident in a single
// wave; all DRAM traffic chip-wide is in flight concurrently. No smem, no barriers.

#define B_TOTAL 512
#define HW 4096
#define NCO 32
#define NCLS 10

__global__ __launch_bounds__(32, 16)
void fused_bnn_kernel(const float* __restrict__ x,
                      const float* __restrict__ conv_w,   // [9,32]
                      const float* __restrict__ conv_b,   // [32]
                      const float* __restrict__ dense_w,  // [32,10]
                      const float* __restrict__ dense_b,  // [10]
                      float* __restrict__ out)            // [512,10]
{
    const int b    = blockIdx.x;
    const int lane = threadIdx.x;          // 32
    const unsigned FULL = 0xffffffffu;
    const float4* img4 = reinterpret_cast<const float4*>(x + (size_t)b * HW); // 1024 float4

    // Lane l handles float4 indices c*32 + l, c = 0..31 (32 x LDG.128, coalesced).
    // float4 f covers floats [4f,4f+4): row = f>>4; f = c*32+l => row = 2c + (l>>4).
    //   row 0  <=> c==0  && l<16 ; row 63 <=> c==31 && l>=16
    //   col 0  <=> (l&15)==0 (x comp) ; col 63 <=> (l&15)==15 (w comp)  [lane-invariant]
    float acc0 = 0.f, acc1 = 0.f, acc2 = 0.f, acc3 = 0.f;
    float colx = 0.f, colw = 0.f;          // per-lane sums of .x / .w comps over all c
    float s0 = 0.f, s31 = 0.f;             // row-chunk sums at c==0 / c==31
    float v0x = 0.f, v0w = 0.f, v31x = 0.f, v31w = 0.f;  // corner carriers

    #pragma unroll
    for (int c = 0; c < 32; c++) {
        float4 v = img4[c * 32 + lane];
        float s = (v.x + v.y) + (v.z + v.w);
        if ((c & 3) == 0) acc0 += s;
        else if ((c & 3) == 1) acc1 += s;
        else if ((c & 3) == 2) acc2 += s;
        else acc3 += s;
        colx += v.x;
        colw += v.w;
        if (c == 0)  { s0  = s; v0x  = v.x; v0w  = v.w; }
        if (c == 31) { s31 = s; v31x = v.x; v31w = v.w; }
    }

    float T   = (acc0 + acc1) + (acc2 + acc3);
    float R0  = (lane < 16)        ? s0   : 0.f;
    float R63 = (lane >= 16)       ? s31  : 0.f;
    float C0  = ((lane & 15) == 0)  ? colx : 0.f;
    float C63 = ((lane & 15) == 15) ? colw : 0.f;

    // Butterfly reductions: every lane ends with the full value.
    #pragma unroll
    for (int off = 16; off > 0; off >>= 1) {
        T   += __shfl_xor_sync(FULL, T,   off);
        R0  += __shfl_xor_sync(FULL, R0,  off);
        R63 += __shfl_xor_sync(FULL, R63, off);
        C0  += __shfl_xor_sync(FULL, C0,  off);
        C63 += __shfl_xor_sync(FULL, C63, off);
    }

    // Corners via shuffle: x[0,0]=lane0 v0x, x[0,63]=lane15 v0w,
    // x[63,0]=lane16 v31x, x[63,63]=lane31 v31w.
    float x00 = __shfl_sync(FULL, v0x,  0);
    float x0e = __shfl_sync(FULL, v0w,  15);
    float xe0 = __shfl_sync(FULL, v31x, 16);
    float xee = __shfl_sync(FULL, v31w, 31);

    // 9 shifted-window sums. k = kh*3+kw; dh=kh-1, dw=kw-1.
    float S[9];
    S[0] = T - R63 - C63 + xee;  S[1] = T - R63;  S[2] = T - R63 - C0 + xe0;
    S[3] = T - C63;              S[4] = T;        S[5] = T - C0;
    S[6] = T - R0  - C63 + x0e;  S[7] = T - R0;   S[8] = T - R0  - C0 + x00;

    // Channel co = lane: p = conv_b + (1/4096) * sum_k sign(conv_w[k,co]) * S[k]
    float acc = 0.f;
    #pragma unroll
    for (int k = 0; k < 9; k++) {
        float w = conv_w[k * NCO + lane];
        acc += (w >= 0.f) ? S[k] : -S[k];
    }
    float p = conv_b[lane] + acc * (1.f / (float)HW);

    // Dense: lanes 0..9 accumulate logits; p broadcast per channel.
    float logit = (lane < NCLS) ? dense_b[lane] : 0.f;
    #pragma unroll
    for (int co = 0; co < NCO; co++) {
        float pc = __shfl_sync(FULL, p, co);
        if (lane < NCLS) logit += pc * dense_w[co * NCLS + lane];
    }

    // Softmax across lanes 0..9.
    float m = (lane < NCLS) ? logit : -INFINITY;
    #pragma unroll
    for (int off = 16; off > 0; off >>= 1)
        m = fmaxf(m, __shfl_xor_sync(FULL, m, off));
    float e = (lane < NCLS) ? expf(logit - m) : 0.f;
    float d = e;
    #pragma unroll
    for (int off = 16; off > 0; off >>= 1)
        d += __shfl_xor_sync(FULL, d, off);

    if (lane < NCLS) out[b * NCLS + lane] = e / d;
}

extern "C" void kernel_launch(void* const* d_in, const int* in_sizes, int n_in,
                              void* d_out, int out_size) {
    const float* x       = (const float*)d_in[0];
    const float* conv_w  = (const float*)d_in[1];
    const float* conv_b  = (const float*)d_in[2];
    const float* dense_w = (const float*)d_in[3];
    const float* dense_b = (const float*)d_in[4];
    float* out = (float*)d_out;
    (void)in_sizes; (void)n_in; (void)out_size;

    fused_bnn_kernel<<<B_TOTAL, 32>>>(x, conv_w, conv_b, dense_w, dense_b, out);
}